// round 6
// baseline (speedup 1.0000x reference)
#include <cuda_runtime.h>
#include <math.h>

#define D_INPUT 118
#define MAXB 524288
#define T1 192

// -------- smem layout (float offsets) --------
#define EW0 0        // 118x60
#define EB0 7080     // 60
#define EW1 7140     // 60x32 (pad of 30)
#define EB1 9060     // 32
#define EW2 9092     // 30x12 (pad of 10)
#define EB2 9452     // 12
#define EW3 9464     // 12 (10 used)
#define EB3 9476     // 4 (1 used)
#define DW0 9480     // 12 (10 used)
#define DB0 9492     // 12
#define DW1 9504     // 10x32 (pad of 30)
#define DB1 9824     // 32
#define DW2 9856     // 30x60
#define DB2 11656    // 60
#define DW3 11716    // 60x120 (pad of 118)
#define DB3 18916    // 120
#define SW0 19036    // 4x10
#define SB0 19076    // 12 (10)
#define SW1 19088    // 10x2
#define SB1 19108    // 4 (2)
#define WTOT 19112
#define XS  19112            // T1 rows, stride 119 (odd -> conflict-free)
#define XSTR 119
#define HB  (XS + T1*XSTR)   // per-thread 61-float scratch (odd stride)
#define HSTR 61
#define SMF (HB + T1*HSTR)
#define SMEM_BYTES (SMF*4)

struct WPtrs { const float* p[20]; };

__device__ double g_acc[32];          // S0[2], S1[2][4], S2[2][10]
__device__ float4 g_z4[MAXB];         // per-row z
__device__ float  g_cp[24];           // mu[2][4], r[2][4], coef[2], maxval

__device__ __forceinline__ void cpW(float* sm, int off, const float* g,
                                    int rows, int cols, int colsP) {
    for (int i = threadIdx.x; i < rows * cols; i += blockDim.x)
        sm[off + (i / cols) * colsP + (i % cols)] = g[i];
}

__global__ void zero_acc_kernel() {
    if (threadIdx.x < 32) g_acc[threadIdx.x] = 0.0;
}

__global__ void __launch_bounds__(T1, 1)
pass1_kernel(const float* __restrict__ x, float* __restrict__ out,
             int Bt, WPtrs W) {
    extern __shared__ float sm[];
    const int tid = threadIdx.x;
    const long long base = (long long)blockIdx.x * T1;
    long long rem = (long long)Bt - base;
    int rowsv = rem < 0 ? 0 : (rem > T1 ? T1 : (int)rem);

    // zero weights + x tile regions (pads must be 0)
    for (int i = tid; i < XS + T1 * XSTR; i += T1) sm[i] = 0.f;
    __syncthreads();

    cpW(sm, EW0, W.p[0], 118, 60, 60);
    cpW(sm, EB0, W.p[1], 1, 60, 60);
    cpW(sm, EW1, W.p[2], 60, 30, 32);
    cpW(sm, EB1, W.p[3], 1, 30, 32);
    cpW(sm, EW2, W.p[4], 30, 10, 12);
    cpW(sm, EB2, W.p[5], 1, 10, 12);
    cpW(sm, EW3, W.p[6], 10, 1, 1);
    cpW(sm, EB3, W.p[7], 1, 1, 1);
    cpW(sm, DW0, W.p[8], 1, 10, 10);
    cpW(sm, DB0, W.p[9], 1, 10, 10);
    cpW(sm, DW1, W.p[10], 10, 30, 32);
    cpW(sm, DB1, W.p[11], 1, 30, 32);
    cpW(sm, DW2, W.p[12], 30, 60, 60);
    cpW(sm, DB2, W.p[13], 1, 60, 60);
    cpW(sm, DW3, W.p[14], 60, 118, 120);
    cpW(sm, DB3, W.p[15], 1, 118, 120);
    cpW(sm, SW0, W.p[16], 4, 10, 10);
    cpW(sm, SB0, W.p[17], 1, 10, 10);
    cpW(sm, SW1, W.p[18], 10, 2, 2);
    cpW(sm, SB1, W.p[19], 1, 2, 2);
    // coalesced x tile load
    for (int i = tid; i < rowsv * 118; i += T1) {
        int r = i / 118, c = i % 118;
        sm[XS + r * XSTR + c] = x[(base + r) * 118 + c];
    }
    __syncthreads();

    float* xr = sm + XS + tid * XSTR;
    float* hb = sm + HB + tid * HSTR;

    // ---- encoder L1: 118 -> 60, relu ----
    float h1[60];
#pragma unroll
    for (int k = 0; k < 60; k += 4) {
        float4 b = *(const float4*)(sm + EB0 + k);
        h1[k] = b.x; h1[k+1] = b.y; h1[k+2] = b.z; h1[k+3] = b.w;
    }
    float sx = 0.f, sx2 = 0.f;
#pragma unroll 2
    for (int j = 0; j < 118; ++j) {
        float xv = xr[j];
        sx += xv; sx2 += xv * xv;
        const float4* w = (const float4*)(sm + EW0 + j * 60);
#pragma unroll
        for (int u = 0; u < 15; ++u) {
            float4 wv = w[u];
            h1[4*u]   += xv * wv.x; h1[4*u+1] += xv * wv.y;
            h1[4*u+2] += xv * wv.z; h1[4*u+3] += xv * wv.w;
        }
    }
#pragma unroll
    for (int k = 0; k < 60; ++k) hb[k] = fmaxf(h1[k], 0.f);

    // ---- encoder L2: 60 -> 30(pad 32), relu (regs) ----
    float h2[32];
#pragma unroll
    for (int k = 0; k < 32; k += 4) {
        float4 b = *(const float4*)(sm + EB1 + k);
        h2[k] = b.x; h2[k+1] = b.y; h2[k+2] = b.z; h2[k+3] = b.w;
    }
#pragma unroll 2
    for (int j = 0; j < 60; ++j) {
        float v = hb[j];
        const float4* w = (const float4*)(sm + EW1 + j * 32);
#pragma unroll
        for (int u = 0; u < 8; ++u) {
            float4 wv = w[u];
            h2[4*u]   += v * wv.x; h2[4*u+1] += v * wv.y;
            h2[4*u+2] += v * wv.z; h2[4*u+3] += v * wv.w;
        }
    }
#pragma unroll
    for (int k = 0; k < 32; ++k) h2[k] = fmaxf(h2[k], 0.f);

    // ---- encoder L3: 30 -> 10(pad 12), relu ----
    float h3[12];
#pragma unroll
    for (int k = 0; k < 12; k += 4) {
        float4 b = *(const float4*)(sm + EB2 + k);
        h3[k] = b.x; h3[k+1] = b.y; h3[k+2] = b.z; h3[k+3] = b.w;
    }
#pragma unroll
    for (int j = 0; j < 30; ++j) {
        float v = h2[j];
        const float4* w = (const float4*)(sm + EW2 + j * 12);
#pragma unroll
        for (int u = 0; u < 3; ++u) {
            float4 wv = w[u];
            h3[4*u]   += v * wv.x; h3[4*u+1] += v * wv.y;
            h3[4*u+2] += v * wv.z; h3[4*u+3] += v * wv.w;
        }
    }
    // ---- enc: 10 -> 1 ----
    float e = sm[EB3];
#pragma unroll
    for (int j = 0; j < 10; ++j) e += fmaxf(h3[j], 0.f) * sm[EW3 + j];

    // ---- decoder L1: 1 -> 10, tanh ----
    float d1v[10];
#pragma unroll
    for (int k = 0; k < 10; ++k) d1v[k] = tanhf(e * sm[DW0 + k] + sm[DB0 + k]);

    // ---- decoder L2: 10 -> 30(pad 32), tanh ----
    float d2v[32];
#pragma unroll
    for (int k = 0; k < 32; k += 4) {
        float4 b = *(const float4*)(sm + DB1 + k);
        d2v[k] = b.x; d2v[k+1] = b.y; d2v[k+2] = b.z; d2v[k+3] = b.w;
    }
#pragma unroll
    for (int j = 0; j < 10; ++j) {
        float v = d1v[j];
        const float4* w = (const float4*)(sm + DW1 + j * 32);
#pragma unroll
        for (int u = 0; u < 8; ++u) {
            float4 wv = w[u];
            d2v[4*u]   += v * wv.x; d2v[4*u+1] += v * wv.y;
            d2v[4*u+2] += v * wv.z; d2v[4*u+3] += v * wv.w;
        }
    }
#pragma unroll
    for (int k = 0; k < 30; ++k) hb[k] = tanhf(d2v[k]);

    // ---- decoder L3: 30 -> 60, tanh ----
    float d3v[60];
#pragma unroll
    for (int k = 0; k < 60; k += 4) {
        float4 b = *(const float4*)(sm + DB2 + k);
        d3v[k] = b.x; d3v[k+1] = b.y; d3v[k+2] = b.z; d3v[k+3] = b.w;
    }
#pragma unroll 2
    for (int j = 0; j < 30; ++j) {
        float v = hb[j];
        const float4* w = (const float4*)(sm + DW2 + j * 60);
#pragma unroll
        for (int u = 0; u < 15; ++u) {
            float4 wv = w[u];
            d3v[4*u]   += v * wv.x; d3v[4*u+1] += v * wv.y;
            d3v[4*u+2] += v * wv.z; d3v[4*u+3] += v * wv.w;
        }
    }
#pragma unroll
    for (int k = 0; k < 60; ++k) hb[k] = tanhf(d3v[k]);

    // ---- decoder L4: 60 -> 118(pad 120) in two 60-wide chunks ----
    float dot = 0.f, dn2 = 0.f, dd2 = 0.f;
#pragma unroll
    for (int c = 0; c < 2; ++c) {
        const int jo = c * 60;
        float dv[60];
#pragma unroll
        for (int k = 0; k < 60; k += 4) {
            float4 b = *(const float4*)(sm + DB3 + jo + k);
            dv[k] = b.x; dv[k+1] = b.y; dv[k+2] = b.z; dv[k+3] = b.w;
        }
#pragma unroll 2
        for (int k = 0; k < 60; ++k) {
            float v = hb[k];
            const float4* w = (const float4*)(sm + DW3 + k * 120 + jo);
#pragma unroll
            for (int u = 0; u < 15; ++u) {
                float4 wv = w[u];
                dv[4*u]   += v * wv.x; dv[4*u+1] += v * wv.y;
                dv[4*u+2] += v * wv.z; dv[4*u+3] += v * wv.w;
            }
        }
#pragma unroll
        for (int i = 0; i < 60; ++i) {
            if (jo + i < 118) {
                float xv = xr[jo + i];
                float d = dv[i];
                dot += xv * d; dn2 += d * d;
                float df = xv - d; dd2 += df * df;
                xr[jo + i] = d;   // overwrite x tile with dec for coalesced store
            }
        }
    }

    // ---- z features ----
    float xn = sqrtf(sx2);
    float dn = sqrtf(dn2);
    float rel = sqrtf(dd2) / fmaxf(xn, 1e-10f);
    float cs = dot / fmaxf(xn * dn, 1e-10f);
    float mean = sx * (1.f / 118.f);
    float var = sx2 * (1.f / 118.f) - mean * mean;
    float sd = sqrtf(fmaxf(var, 0.f));
    float z0 = e, z1 = rel, z2 = cs, z3 = sd;

    // ---- estimation net: 4 -> 10 tanh -> 2 softmax ----
    float l0 = sm[SB1], l1 = sm[SB1 + 1];
#pragma unroll
    for (int k = 0; k < 10; ++k) {
        float t = tanhf(z0 * sm[SW0 + k] + z1 * sm[SW0 + 10 + k] +
                        z2 * sm[SW0 + 20 + k] + z3 * sm[SW0 + 30 + k] +
                        sm[SB0 + k]);
        l0 += t * sm[SW1 + 2 * k];
        l1 += t * sm[SW1 + 2 * k + 1];
    }
    float mx = fmaxf(l0, l1);
    float e0 = expf(l0 - mx), e1 = expf(l1 - mx);
    float sinv = 1.f / (e0 + e1);
    float gg0 = e0 * sinv, gg1 = e1 * sinv;

    bool valid = tid < rowsv;
    if (valid) {
        g_z4[base + tid] = make_float4(z0, z1, z2, z3);
    } else {
        gg0 = gg1 = 0.f; z0 = z1 = z2 = z3 = 0.f;
    }

    // ---- 30-way global reduction: S0, S1, sym S2 ----
    float red[30];
    red[0] = gg0; red[1] = gg1;
    red[2] = gg0 * z0; red[3] = gg0 * z1; red[4] = gg0 * z2; red[5] = gg0 * z3;
    red[6] = gg1 * z0; red[7] = gg1 * z1; red[8] = gg1 * z2; red[9] = gg1 * z3;
    {
        float zz[10] = { z0*z0, z0*z1, z0*z2, z0*z3, z1*z1,
                         z1*z2, z1*z3, z2*z2, z2*z3, z3*z3 };
#pragma unroll
        for (int p = 0; p < 10; ++p) { red[10+p] = gg0*zz[p]; red[20+p] = gg1*zz[p]; }
    }
#pragma unroll
    for (int r = 0; r < 30; ++r) {
        float v = red[r];
        v += __shfl_xor_sync(0xffffffffu, v, 16);
        v += __shfl_xor_sync(0xffffffffu, v, 8);
        v += __shfl_xor_sync(0xffffffffu, v, 4);
        v += __shfl_xor_sync(0xffffffffu, v, 2);
        v += __shfl_xor_sync(0xffffffffu, v, 1);
        if ((tid & 31) == 0) atomicAdd(&g_acc[r], (double)v);
    }

    __syncthreads();
    // coalesced dec store
    for (int i = tid; i < rowsv * 118; i += T1) {
        int r = i / 118, c = i % 118;
        out[(base + r) * 118 + c] = sm[XS + r * XSTR + c];
    }
}

__device__ double inv4x4(const double m[16], double inv[16]) {
    inv[0]  =  m[5]*m[10]*m[15] - m[5]*m[11]*m[14] - m[9]*m[6]*m[15] + m[9]*m[7]*m[14] + m[13]*m[6]*m[11] - m[13]*m[7]*m[10];
    inv[4]  = -m[4]*m[10]*m[15] + m[4]*m[11]*m[14] + m[8]*m[6]*m[15] - m[8]*m[7]*m[14] - m[12]*m[6]*m[11] + m[12]*m[7]*m[10];
    inv[8]  =  m[4]*m[9]*m[15]  - m[4]*m[11]*m[13] - m[8]*m[5]*m[15] + m[8]*m[7]*m[13] + m[12]*m[5]*m[11] - m[12]*m[7]*m[9];
    inv[12] = -m[4]*m[9]*m[14]  + m[4]*m[10]*m[13] + m[8]*m[5]*m[14] - m[8]*m[6]*m[13] - m[12]*m[5]*m[10] + m[12]*m[6]*m[9];
    inv[1]  = -m[1]*m[10]*m[15] + m[1]*m[11]*m[14] + m[9]*m[2]*m[15] - m[9]*m[3]*m[14] - m[13]*m[2]*m[11] + m[13]*m[3]*m[10];
    inv[5]  =  m[0]*m[10]*m[15] - m[0]*m[11]*m[14] - m[8]*m[2]*m[15] + m[8]*m[3]*m[14] + m[12]*m[2]*m[11] - m[12]*m[3]*m[10];
    inv[9]  = -m[0]*m[9]*m[15]  + m[0]*m[11]*m[13] + m[8]*m[1]*m[15] - m[8]*m[3]*m[13] - m[12]*m[1]*m[11] + m[12]*m[3]*m[9];
    inv[13] =  m[0]*m[9]*m[14]  - m[0]*m[10]*m[13] - m[8]*m[1]*m[14] + m[8]*m[2]*m[13] + m[12]*m[1]*m[10] - m[12]*m[2]*m[9];
    inv[2]  =  m[1]*m[6]*m[15]  - m[1]*m[7]*m[14]  - m[5]*m[2]*m[15] + m[5]*m[3]*m[14] + m[13]*m[2]*m[7]  - m[13]*m[3]*m[6];
    inv[6]  = -m[0]*m[6]*m[15]  + m[0]*m[7]*m[14]  + m[4]*m[2]*m[15] - m[4]*m[3]*m[14] - m[12]*m[2]*m[7]  + m[12]*m[3]*m[6];
    inv[10] =  m[0]*m[5]*m[15]  - m[0]*m[7]*m[13]  - m[4]*m[1]*m[15] + m[4]*m[3]*m[13] + m[12]*m[1]*m[7]  - m[12]*m[3]*m[5];
    inv[14] = -m[0]*m[5]*m[14]  + m[0]*m[6]*m[13]  + m[4]*m[1]*m[14] - m[4]*m[2]*m[13] - m[12]*m[1]*m[6]  + m[12]*m[2]*m[5];
    inv[3]  = -m[1]*m[6]*m[11]  + m[1]*m[7]*m[10]  + m[5]*m[2]*m[11] - m[5]*m[3]*m[10] - m[9]*m[2]*m[7]   + m[9]*m[3]*m[6];
    inv[7]  =  m[0]*m[6]*m[11]  - m[0]*m[7]*m[10]  - m[4]*m[2]*m[11] + m[4]*m[3]*m[10] + m[8]*m[2]*m[7]   - m[8]*m[3]*m[6];
    inv[11] = -m[0]*m[5]*m[11]  + m[0]*m[7]*m[9]   + m[4]*m[1]*m[11] - m[4]*m[3]*m[9]  - m[8]*m[1]*m[7]   + m[8]*m[3]*m[5];
    inv[15] =  m[0]*m[5]*m[10]  - m[0]*m[6]*m[9]   - m[4]*m[1]*m[10] + m[4]*m[2]*m[9]  + m[8]*m[1]*m[6]   - m[8]*m[2]*m[5];
    double det = m[0]*inv[0] + m[1]*inv[4] + m[2]*inv[8] + m[3]*inv[12];
    double id = 1.0 / det;
    for (int i = 0; i < 16; ++i) inv[i] *= id;
    return det;
}

__global__ void pass2_kernel(float* out, int Bt) {
    if (blockIdx.x != 0 || threadIdx.x != 0) return;
    double Sg[2], S1[2][4], S2[2][10];
    Sg[0] = g_acc[0]; Sg[1] = g_acc[1];
    for (int k = 0; k < 2; ++k) {
        for (int c = 0; c < 4; ++c) S1[k][c] = g_acc[2 + k * 4 + c];
        for (int p = 0; p < 10; ++p) S2[k][p] = g_acc[10 + k * 10 + p];
    }
    const int pi[10] = {0,0,0,0,1,1,1,2,2,3};
    const int pj[10] = {0,1,2,3,1,2,3,2,3,3};
    double mu[2][4], rr[2][4], coef[2];
    double covdiag = 0.0;
    const double TP = 6.283185307179586476925287;
    const double scale4 = TP * TP * TP * TP;
    for (int k = 0; k < 2; ++k) {
        for (int c = 0; c < 4; ++c) mu[k][c] = S1[k][c] / Sg[k];
        double m[16];
        for (int p = 0; p < 10; ++p) {
            double cv = S2[k][p] / Sg[k] - mu[k][pi[p]] * mu[k][pj[p]];
            if (pi[p] == pj[p]) cv += 1e-12;
            m[pi[p] * 4 + pj[p]] = cv;
            m[pj[p] * 4 + pi[p]] = cv;
        }
        for (int i = 0; i < 4; ++i) covdiag += 1.0 / m[i * 4 + i];
        double inv[16];
        double det = inv4x4(m, inv);
        double detcov = det * scale4;
        double phi = Sg[k] / (double)Bt;
        coef[k] = phi / (sqrt(detcov) + 1e-12);
        for (int g = 0; g < 4; ++g)
            rr[k][g] = inv[g*4+0] + inv[g*4+1] + inv[g*4+2] + inv[g*4+3];
    }
    float4 zf = g_z4[0];
    double z0[4] = { zf.x, zf.y, zf.z, zf.w };
    double mv = 0.0;
    for (int k = 0; k < 2; ++k) {
        double s1 = 0.0, dot = 0.0;
        for (int c = 0; c < 4; ++c) {
            double zm = z0[c] - mu[k][c];
            s1 += zm; dot += zm * rr[k][c];
        }
        double ett = -0.5 * dot * s1;
        if (ett > mv) mv = ett;
    }
    for (int k = 0; k < 2; ++k) {
        for (int c = 0; c < 4; ++c) {
            g_cp[k * 4 + c] = (float)mu[k][c];
            g_cp[8 + k * 4 + c] = (float)rr[k][c];
        }
        g_cp[16 + k] = (float)coef[k];
    }
    g_cp[18] = (float)mv;
    out[(size_t)Bt * 118 + Bt] = (float)covdiag;
}

__global__ void pass3_kernel(float* __restrict__ out, int Bt) {
    int b = blockIdx.x * blockDim.x + threadIdx.x;
    if (b >= Bt) return;
    float4 z = g_z4[b];
    float mv = g_cp[18];
    float s = 0.f;
#pragma unroll
    for (int k = 0; k < 2; ++k) {
        float zm0 = z.x - g_cp[k*4+0];
        float zm1 = z.y - g_cp[k*4+1];
        float zm2 = z.z - g_cp[k*4+2];
        float zm3 = z.w - g_cp[k*4+3];
        float s1 = zm0 + zm1 + zm2 + zm3;
        float dot = zm0 * g_cp[8+k*4+0] + zm1 * g_cp[8+k*4+1] +
                    zm2 * g_cp[8+k*4+2] + zm3 * g_cp[8+k*4+3];
        float ett = -0.5f * dot * s1;
        float t = fminf(fmaxf(ett - mv, -50.f), 50.f);
        s += g_cp[16+k] * expf(t);
    }
    out[(size_t)Bt * 118 + b] = -mv - logf(s + 1e-12f);
}

extern "C" void kernel_launch(void* const* d_in, const int* in_sizes, int n_in,
                              void* d_out, int out_size) {
    const float* x = (const float*)d_in[0];
    WPtrs W;
    for (int i = 0; i < 20; ++i) W.p[i] = (const float*)d_in[1 + i];
    int Bt = in_sizes[0] / 118;
    if (Bt > MAXB) Bt = MAXB;
    float* out = (float*)d_out;

    (void)cudaFuncSetAttribute(pass1_kernel,
                               cudaFuncAttributeMaxDynamicSharedMemorySize,
                               SMEM_BYTES);

    zero_acc_kernel<<<1, 32>>>();
    int grid = (Bt + T1 - 1) / T1;
    pass1_kernel<<<grid, T1, SMEM_BYTES>>>(x, out, Bt, W);
    pass2_kernel<<<1, 1>>>(out, Bt);
    pass3_kernel<<<(Bt + 255) / 256, 256>>>(out, Bt);
}

// round 10
// speedup vs baseline: 1.2248x; 1.2248x over previous
#include <cuda_runtime.h>
#include <math.h>

#define D_INPUT 118
#define MAXB 524288
#define T1 256

// -------- smem layout (float offsets) --------
#define EW0 0        // 118x60
#define EB0 7080     // 60
#define EW1 7140     // 60x32 (pad of 30)
#define EB1 9060     // 32
#define EW2 9092     // 30x12 (pad of 10)
#define EB2 9452     // 12
#define EW3 9464     // 12 (10 used)
#define EB3 9476     // 4 (1 used)
#define DW0 9480     // 12 (10 used)
#define DB0 9492     // 12
#define DW1 9504     // 10x32 (pad of 30)
#define DB1 9824     // 32
#define DW2 9856     // 30x60
#define DB2 11656    // 60
#define DW3 11716    // 60x120 (pad of 118)
#define DB3 18916    // 120
#define SW0 19036    // 4x10
#define SB0 19076    // 12 (10)
#define SW1 19088    // 10x2
#define SB1 19108    // 4 (2)
#define XS  19112            // T1 rows, stride 119 (odd -> conflict-free)
#define XSTR 119
#define REDS (XS + T1*XSTR)  // 8 warps x 30 partial sums
#define SMF  (REDS + 8*30)
#define SMEM_BYTES (SMF*4)

struct WPtrs { const float* p[20]; };

__device__ double g_acc[32];          // S0[2], S1[2][4], S2[2][10]
__device__ float4 g_z4[MAXB];         // per-row z
__device__ float  g_cp[24];           // mu[2][4], r[2][4], coef[2], maxval

__device__ __forceinline__ float ftanh(float x) {
    float c = fminf(fmaxf(x, -15.f), 15.f);
    float e = __expf(2.f * c);
    return 1.f - __fdividef(2.f, e + 1.f);
}

__device__ __forceinline__ void cpW(float* sm, int off, const float* g,
                                    int rows, int cols, int colsP) {
    for (int i = threadIdx.x; i < rows * cols; i += blockDim.x)
        sm[off + (i / cols) * colsP + (i % cols)] = g[i];
}

__global__ void zero_acc_kernel() {
    if (threadIdx.x < 32) g_acc[threadIdx.x] = 0.0;
}

__global__ void __launch_bounds__(T1, 1)
pass1_kernel(const float* __restrict__ x, float* __restrict__ out,
             int Bt, WPtrs W) {
    extern __shared__ float sm[];
    const int tid = threadIdx.x;
    const long long base = (long long)blockIdx.x * T1;
    long long rem = (long long)Bt - base;
    int rowsv = rem < 0 ? 0 : (rem > T1 ? T1 : (int)rem);

    // zero weight pads + x tile
    for (int i = tid; i < XS + T1 * XSTR; i += T1) sm[i] = 0.f;
    __syncthreads();

    cpW(sm, EW0, W.p[0], 118, 60, 60);
    cpW(sm, EB0, W.p[1], 1, 60, 60);
    cpW(sm, EW1, W.p[2], 60, 30, 32);
    cpW(sm, EB1, W.p[3], 1, 30, 32);
    cpW(sm, EW2, W.p[4], 30, 10, 12);
    cpW(sm, EB2, W.p[5], 1, 10, 12);
    cpW(sm, EW3, W.p[6], 10, 1, 1);
    cpW(sm, EB3, W.p[7], 1, 1, 1);
    cpW(sm, DW0, W.p[8], 1, 10, 10);
    cpW(sm, DB0, W.p[9], 1, 10, 10);
    cpW(sm, DW1, W.p[10], 10, 30, 32);
    cpW(sm, DB1, W.p[11], 1, 30, 32);
    cpW(sm, DW2, W.p[12], 30, 60, 60);
    cpW(sm, DB2, W.p[13], 1, 60, 60);
    cpW(sm, DW3, W.p[14], 60, 118, 120);
    cpW(sm, DB3, W.p[15], 1, 118, 120);
    cpW(sm, SW0, W.p[16], 4, 10, 10);
    cpW(sm, SB0, W.p[17], 1, 10, 10);
    cpW(sm, SW1, W.p[18], 10, 2, 2);
    cpW(sm, SB1, W.p[19], 1, 2, 2);
    for (int i = tid; i < rowsv * 118; i += T1) {
        int r = i / 118, c = i % 118;
        sm[XS + r * XSTR + c] = x[(base + r) * 118 + c];
    }
    __syncthreads();

    float* xr = sm + XS + tid * XSTR;

    // ---- encoder L1: 118 -> 60, relu ----
    float h1[60];
#pragma unroll
    for (int k = 0; k < 60; k += 4) {
        float4 b = *(const float4*)(sm + EB0 + k);
        h1[k] = b.x; h1[k+1] = b.y; h1[k+2] = b.z; h1[k+3] = b.w;
    }
    float sx = 0.f, sx2 = 0.f;
#pragma unroll 2
    for (int j = 0; j < 118; ++j) {
        float xv = xr[j];
        sx += xv; sx2 = fmaf(xv, xv, sx2);
        const float4* w = (const float4*)(sm + EW0 + j * 60);
#pragma unroll
        for (int u = 0; u < 15; ++u) {
            float4 wv = w[u];
            h1[4*u]   = fmaf(xv, wv.x, h1[4*u]);
            h1[4*u+1] = fmaf(xv, wv.y, h1[4*u+1]);
            h1[4*u+2] = fmaf(xv, wv.z, h1[4*u+2]);
            h1[4*u+3] = fmaf(xv, wv.w, h1[4*u+3]);
        }
    }
#pragma unroll
    for (int k = 0; k < 60; ++k) h1[k] = fmaxf(h1[k], 0.f);

    // ---- encoder L2: 60 -> 30(pad 32), relu ----
    float h2[32];
#pragma unroll
    for (int k = 0; k < 32; k += 4) {
        float4 b = *(const float4*)(sm + EB1 + k);
        h2[k] = b.x; h2[k+1] = b.y; h2[k+2] = b.z; h2[k+3] = b.w;
    }
#pragma unroll 2
    for (int j = 0; j < 60; ++j) {
        float v = h1[j];
        const float4* w = (const float4*)(sm + EW1 + j * 32);
#pragma unroll
        for (int u = 0; u < 8; ++u) {
            float4 wv = w[u];
            h2[4*u]   = fmaf(v, wv.x, h2[4*u]);
            h2[4*u+1] = fmaf(v, wv.y, h2[4*u+1]);
            h2[4*u+2] = fmaf(v, wv.z, h2[4*u+2]);
            h2[4*u+3] = fmaf(v, wv.w, h2[4*u+3]);
        }
    }
#pragma unroll
    for (int k = 0; k < 32; ++k) h2[k] = fmaxf(h2[k], 0.f);

    // ---- encoder L3: 30 -> 10(pad 12), relu ----
    float h3[12];
#pragma unroll
    for (int k = 0; k < 12; k += 4) {
        float4 b = *(const float4*)(sm + EB2 + k);
        h3[k] = b.x; h3[k+1] = b.y; h3[k+2] = b.z; h3[k+3] = b.w;
    }
#pragma unroll
    for (int j = 0; j < 30; ++j) {
        float v = h2[j];
        const float4* w = (const float4*)(sm + EW2 + j * 12);
#pragma unroll
        for (int u = 0; u < 3; ++u) {
            float4 wv = w[u];
            h3[4*u]   = fmaf(v, wv.x, h3[4*u]);
            h3[4*u+1] = fmaf(v, wv.y, h3[4*u+1]);
            h3[4*u+2] = fmaf(v, wv.z, h3[4*u+2]);
            h3[4*u+3] = fmaf(v, wv.w, h3[4*u+3]);
        }
    }
    // ---- enc: 10 -> 1 ----
    float e = sm[EB3];
#pragma unroll
    for (int j = 0; j < 10; ++j) e = fmaf(fmaxf(h3[j], 0.f), sm[EW3 + j], e);

    // ---- decoder L1: 1 -> 10, tanh ----
    float d1v[10];
#pragma unroll
    for (int k = 0; k < 10; ++k) d1v[k] = ftanh(fmaf(e, sm[DW0 + k], sm[DB0 + k]));

    // ---- decoder L2: 10 -> 30(pad 32), tanh ----
    float d2v[32];
#pragma unroll
    for (int k = 0; k < 32; k += 4) {
        float4 b = *(const float4*)(sm + DB1 + k);
        d2v[k] = b.x; d2v[k+1] = b.y; d2v[k+2] = b.z; d2v[k+3] = b.w;
    }
#pragma unroll
    for (int j = 0; j < 10; ++j) {
        float v = d1v[j];
        const float4* w = (const float4*)(sm + DW1 + j * 32);
#pragma unroll
        for (int u = 0; u < 8; ++u) {
            float4 wv = w[u];
            d2v[4*u]   = fmaf(v, wv.x, d2v[4*u]);
            d2v[4*u+1] = fmaf(v, wv.y, d2v[4*u+1]);
            d2v[4*u+2] = fmaf(v, wv.z, d2v[4*u+2]);
            d2v[4*u+3] = fmaf(v, wv.w, d2v[4*u+3]);
        }
    }
    float d2[30];
#pragma unroll
    for (int k = 0; k < 30; ++k) d2[k] = ftanh(d2v[k]);

    // ---- decoder L3: 30 -> 60, tanh ----
    float d3[60];
#pragma unroll
    for (int k = 0; k < 60; k += 4) {
        float4 b = *(const float4*)(sm + DB2 + k);
        d3[k] = b.x; d3[k+1] = b.y; d3[k+2] = b.z; d3[k+3] = b.w;
    }
#pragma unroll 2
    for (int j = 0; j < 30; ++j) {
        float v = d2[j];
        const float4* w = (const float4*)(sm + DW2 + j * 60);
#pragma unroll
        for (int u = 0; u < 15; ++u) {
            float4 wv = w[u];
            d3[4*u]   = fmaf(v, wv.x, d3[4*u]);
            d3[4*u+1] = fmaf(v, wv.y, d3[4*u+1]);
            d3[4*u+2] = fmaf(v, wv.z, d3[4*u+2]);
            d3[4*u+3] = fmaf(v, wv.w, d3[4*u+3]);
        }
    }
#pragma unroll
    for (int k = 0; k < 60; ++k) d3[k] = ftanh(d3[k]);

    // ---- decoder L4: 60 -> 118(pad 120), two 60-wide chunks ----
    float dot = 0.f, dn2 = 0.f, dd2 = 0.f;
#pragma unroll
    for (int c = 0; c < 2; ++c) {
        const int jo = c * 60;
        float dv[60];
#pragma unroll
        for (int k = 0; k < 60; k += 4) {
            float4 b = *(const float4*)(sm + DB3 + jo + k);
            dv[k] = b.x; dv[k+1] = b.y; dv[k+2] = b.z; dv[k+3] = b.w;
        }
#pragma unroll 2
        for (int k = 0; k < 60; ++k) {
            float v = d3[k];
            const float4* w = (const float4*)(sm + DW3 + k * 120 + jo);
#pragma unroll
            for (int u = 0; u < 15; ++u) {
                float4 wv = w[u];
                dv[4*u]   = fmaf(v, wv.x, dv[4*u]);
                dv[4*u+1] = fmaf(v, wv.y, dv[4*u+1]);
                dv[4*u+2] = fmaf(v, wv.z, dv[4*u+2]);
                dv[4*u+3] = fmaf(v, wv.w, dv[4*u+3]);
            }
        }
#pragma unroll
        for (int i = 0; i < 60; ++i) {
            if (jo + i < 118) {
                float xv = xr[jo + i];
                float d = dv[i];
                dot = fmaf(xv, d, dot); dn2 = fmaf(d, d, dn2);
                float df = xv - d; dd2 = fmaf(df, df, dd2);
                xr[jo + i] = d;   // overwrite x tile with dec for coalesced store
            }
        }
    }

    // ---- z features ----
    float xn = sqrtf(sx2);
    float dn = sqrtf(dn2);
    float rel = sqrtf(dd2) / fmaxf(xn, 1e-10f);
    float cs = dot / fmaxf(xn * dn, 1e-10f);
    float mean = sx * (1.f / 118.f);
    float var = sx2 * (1.f / 118.f) - mean * mean;
    float sd = sqrtf(fmaxf(var, 0.f));
    float z0 = e, z1 = rel, z2 = cs, z3 = sd;

    // ---- estimation net: 4 -> 10 tanh -> 2 softmax ----
    float l0 = sm[SB1], l1 = sm[SB1 + 1];
#pragma unroll
    for (int k = 0; k < 10; ++k) {
        float t = ftanh(z0 * sm[SW0 + k] + z1 * sm[SW0 + 10 + k] +
                        z2 * sm[SW0 + 20 + k] + z3 * sm[SW0 + 30 + k] +
                        sm[SB0 + k]);
        l0 = fmaf(t, sm[SW1 + 2 * k], l0);
        l1 = fmaf(t, sm[SW1 + 2 * k + 1], l1);
    }
    float mx = fmaxf(l0, l1);
    float e0 = __expf(l0 - mx), e1 = __expf(l1 - mx);
    float sinv = __fdividef(1.f, e0 + e1);
    float gg0 = e0 * sinv, gg1 = e1 * sinv;

    bool valid = tid < rowsv;
    if (valid) {
        g_z4[base + tid] = make_float4(z0, z1, z2, z3);
    } else {
        gg0 = gg1 = 0.f; z0 = z1 = z2 = z3 = 0.f;
    }

    // ---- 30-way reduction: warp shuffle -> smem stage -> 30 atomics/block ----
    float red[30];
    red[0] = gg0; red[1] = gg1;
    red[2] = gg0 * z0; red[3] = gg0 * z1; red[4] = gg0 * z2; red[5] = gg0 * z3;
    red[6] = gg1 * z0; red[7] = gg1 * z1; red[8] = gg1 * z2; red[9] = gg1 * z3;
    {
        float zz[10] = { z0*z0, z0*z1, z0*z2, z0*z3, z1*z1,
                         z1*z2, z1*z3, z2*z2, z2*z3, z3*z3 };
#pragma unroll
        for (int p = 0; p < 10; ++p) { red[10+p] = gg0*zz[p]; red[20+p] = gg1*zz[p]; }
    }
    const int wid = tid >> 5;
#pragma unroll
    for (int r = 0; r < 30; ++r) {
        float v = red[r];
        v += __shfl_xor_sync(0xffffffffu, v, 16);
        v += __shfl_xor_sync(0xffffffffu, v, 8);
        v += __shfl_xor_sync(0xffffffffu, v, 4);
        v += __shfl_xor_sync(0xffffffffu, v, 2);
        v += __shfl_xor_sync(0xffffffffu, v, 1);
        if ((tid & 31) == 0) sm[REDS + wid * 30 + r] = v;
    }

    __syncthreads();
    if (tid < 30) {
        float s = 0.f;
#pragma unroll
        for (int w = 0; w < 8; ++w) s += sm[REDS + w * 30 + tid];
        atomicAdd(&g_acc[tid], (double)s);
    }
    // coalesced dec store (x tile now holds dec)
    for (int i = tid; i < rowsv * 118; i += T1) {
        int r = i / 118, c = i % 118;
        out[(base + r) * 118 + c] = sm[XS + r * XSTR + c];
    }
}

__device__ double inv4x4(const double m[16], double inv[16]) {
    inv[0]  =  m[5]*m[10]*m[15] - m[5]*m[11]*m[14] - m[9]*m[6]*m[15] + m[9]*m[7]*m[14] + m[13]*m[6]*m[11] - m[13]*m[7]*m[10];
    inv[4]  = -m[4]*m[10]*m[15] + m[4]*m[11]*m[14] + m[8]*m[6]*m[15] - m[8]*m[7]*m[14] - m[12]*m[6]*m[11] + m[12]*m[7]*m[10];
    inv[8]  =  m[4]*m[9]*m[15]  - m[4]*m[11]*m[13] - m[8]*m[5]*m[15] + m[8]*m[7]*m[13] + m[12]*m[5]*m[11] - m[12]*m[7]*m[9];
    inv[12] = -m[4]*m[9]*m[14]  + m[4]*m[10]*m[13] + m[8]*m[5]*m[14] - m[8]*m[6]*m[13] - m[12]*m[5]*m[10] + m[12]*m[6]*m[9];
    inv[1]  = -m[1]*m[10]*m[15] + m[1]*m[11]*m[14] + m[9]*m[2]*m[15] - m[9]*m[3]*m[14] - m[13]*m[2]*m[11] + m[13]*m[3]*m[10];
    inv[5]  =  m[0]*m[10]*m[15] - m[0]*m[11]*m[14] - m[8]*m[2]*m[15] + m[8]*m[3]*m[14] + m[12]*m[2]*m[11] - m[12]*m[3]*m[10];
    inv[9]  = -m[0]*m[9]*m[15]  + m[0]*m[11]*m[13] + m[8]*m[1]*m[15] - m[8]*m[3]*m[13] - m[12]*m[1]*m[11] + m[12]*m[3]*m[9];
    inv[13] =  m[0]*m[9]*m[14]  - m[0]*m[10]*m[13] - m[8]*m[1]*m[14] + m[8]*m[2]*m[13] + m[12]*m[1]*m[10] - m[12]*m[2]*m[9];
    inv[2]  =  m[1]*m[6]*m[15]  - m[1]*m[7]*m[14]  - m[5]*m[2]*m[15] + m[5]*m[3]*m[14] + m[13]*m[2]*m[7]  - m[13]*m[3]*m[6];
    inv[6]  = -m[0]*m[6]*m[15]  + m[0]*m[7]*m[14]  + m[4]*m[2]*m[15] - m[4]*m[3]*m[14] - m[12]*m[2]*m[7]  + m[12]*m[3]*m[6];
    inv[10] =  m[0]*m[5]*m[15]  - m[0]*m[7]*m[13]  - m[4]*m[1]*m[15] + m[4]*m[3]*m[13] + m[12]*m[1]*m[7]  - m[12]*m[3]*m[5];
    inv[14] = -m[0]*m[5]*m[14]  + m[0]*m[6]*m[13]  + m[4]*m[1]*m[14] - m[4]*m[2]*m[13] - m[12]*m[1]*m[6]  + m[12]*m[2]*m[5];
    inv[3]  = -m[1]*m[6]*m[11]  + m[1]*m[7]*m[10]  + m[5]*m[2]*m[11] - m[5]*m[3]*m[10] - m[9]*m[2]*m[7]   + m[9]*m[3]*m[6];
    inv[7]  =  m[0]*m[6]*m[11]  - m[0]*m[7]*m[10]  - m[4]*m[2]*m[11] + m[4]*m[3]*m[10] + m[8]*m[2]*m[7]   - m[8]*m[3]*m[6];
    inv[11] = -m[0]*m[5]*m[11]  + m[0]*m[7]*m[9]   + m[4]*m[1]*m[11] - m[4]*m[3]*m[9]  - m[8]*m[1]*m[7]   + m[8]*m[3]*m[5];
    inv[15] =  m[0]*m[5]*m[10]  - m[0]*m[6]*m[9]   - m[4]*m[1]*m[10] + m[4]*m[2]*m[9]  + m[8]*m[1]*m[6]   - m[8]*m[2]*m[5];
    double det = m[0]*inv[0] + m[1]*inv[4] + m[2]*inv[8] + m[3]*inv[12];
    double id = 1.0 / det;
    for (int i = 0; i < 16; ++i) inv[i] *= id;
    return det;
}

__global__ void pass2_kernel(float* out, int Bt) {
    if (blockIdx.x != 0 || threadIdx.x != 0) return;
    double Sg[2], S1[2][4], S2[2][10];
    Sg[0] = g_acc[0]; Sg[1] = g_acc[1];
    for (int k = 0; k < 2; ++k) {
        for (int c = 0; c < 4; ++c) S1[k][c] = g_acc[2 + k * 4 + c];
        for (int p = 0; p < 10; ++p) S2[k][p] = g_acc[10 + k * 10 + p];
    }
    const int pi[10] = {0,0,0,0,1,1,1,2,2,3};
    const int pj[10] = {0,1,2,3,1,2,3,2,3,3};
    double mu[2][4], rr[2][4], coef[2];
    double covdiag = 0.0;
    const double TP = 6.283185307179586476925287;
    const double scale4 = TP * TP * TP * TP;
    for (int k = 0; k < 2; ++k) {
        for (int c = 0; c < 4; ++c) mu[k][c] = S1[k][c] / Sg[k];
        double m[16];
        for (int p = 0; p < 10; ++p) {
            double cv = S2[k][p] / Sg[k] - mu[k][pi[p]] * mu[k][pj[p]];
            if (pi[p] == pj[p]) cv += 1e-12;
            m[pi[p] * 4 + pj[p]] = cv;
            m[pj[p] * 4 + pi[p]] = cv;
        }
        for (int i = 0; i < 4; ++i) covdiag += 1.0 / m[i * 4 + i];
        double inv[16];
        double det = inv4x4(m, inv);
        double detcov = det * scale4;
        double phi = Sg[k] / (double)Bt;
        coef[k] = phi / (sqrt(detcov) + 1e-12);
        for (int g = 0; g < 4; ++g)
            rr[k][g] = inv[g*4+0] + inv[g*4+1] + inv[g*4+2] + inv[g*4+3];
    }
    float4 zf = g_z4[0];
    double z0[4] = { zf.x, zf.y, zf.z, zf.w };
    double mv = 0.0;
    for (int k = 0; k < 2; ++k) {
        double s1 = 0.0, dot = 0.0;
        for (int c = 0; c < 4; ++c) {
            double zm = z0[c] - mu[k][c];
            s1 += zm; dot += zm * rr[k][c];
        }
        double ett = -0.5 * dot * s1;
        if (ett > mv) mv = ett;
    }
    for (int k = 0; k < 2; ++k) {
        for (int c = 0; c < 4; ++c) {
            g_cp[k * 4 + c] = (float)mu[k][c];
            g_cp[8 + k * 4 + c] = (float)rr[k][c];
        }
        g_cp[16 + k] = (float)coef[k];
    }
    g_cp[18] = (float)mv;
    out[(size_t)Bt * 118 + Bt] = (float)covdiag;
}

__global__ void pass3_kernel(float* __restrict__ out, int Bt) {
    int b = blockIdx.x * blockDim.x + threadIdx.x;
    if (b >= Bt) return;
    float4 z = g_z4[b];
    float mv = g_cp[18];
    float s = 0.f;
#pragma unroll
    for (int k = 0; k < 2; ++k) {
        float zm0 = z.x - g_cp[k*4+0];
        float zm1 = z.y - g_cp[k*4+1];
        float zm2 = z.z - g_cp[k*4+2];
        float zm3 = z.w - g_cp[k*4+3];
        float s1 = zm0 + zm1 + zm2 + zm3;
        float dot = zm0 * g_cp[8+k*4+0] + zm1 * g_cp[8+k*4+1] +
                    zm2 * g_cp[8+k*4+2] + zm3 * g_cp[8+k*4+3];
        float ett = -0.5f * dot * s1;
        float t = fminf(fmaxf(ett - mv, -50.f), 50.f);
        s += g_cp[16+k] * expf(t);
    }
    out[(size_t)Bt * 118 + b] = -mv - logf(s + 1e-12f);
}

extern "C" void kernel_launch(void* const* d_in, const int* in_sizes, int n_in,
                              void* d_out, int out_size) {
    const float* x = (const float*)d_in[0];
    WPtrs W;
    for (int i = 0; i < 20; ++i) W.p[i] = (const float*)d_in[1 + i];
    int Bt = in_sizes[0] / 118;
    if (Bt > MAXB) Bt = MAXB;
    float* out = (float*)d_out;

    (void)cudaFuncSetAttribute(pass1_kernel,
                               cudaFuncAttributeMaxDynamicSharedMemorySize,
                               SMEM_BYTES);

    zero_acc_kernel<<<1, 32>>>();
    int grid = (Bt + T1 - 1) / T1;
    pass1_kernel<<<grid, T1, SMEM_BYTES>>>(x, out, Bt, W);
    pass2_kernel<<<1, 1>>>(out, Bt);
    pass3_kernel<<<(Bt + 255) / 256, 256>>>(out, Bt);
}

// round 11
// speedup vs baseline: 1.2971x; 1.0590x over previous
#include <cuda_runtime.h>
#include <math.h>

#define D_INPUT 118
#define MAXB 524288
#define T1 256

// -------- smem layout (float offsets) --------
#define EW0 0        // 118x60
#define EB0 7080     // 60
#define EW1 7140     // 60x32 (pad of 30)
#define EB1 9060     // 32
#define EW2 9092     // 30x12 (pad of 10)
#define EB2 9452     // 12
#define EW3 9464     // 12 (10 used)
#define EB3 9476     // 4 (1 used)
#define DW0 9480     // 12 (10 used)
#define DB0 9492     // 12
#define DW1 9504     // 10x32 (pad of 30)
#define DB1 9824     // 32
#define DW2 9856     // 30x60
#define DB2 11656    // 60
#define DW3 11716    // 60x120 (pad of 118)
#define DB3 18916    // 120
#define SW0 19036    // 4x10
#define SB0 19076    // 12 (10)
#define SW1 19088    // 10x2
#define SB1 19108    // 4 (2)
#define XS  19112            // T1 rows, stride 119 (odd -> conflict-free)
#define XSTR 119
#define REDS (XS + T1*XSTR)  // 8 warps x 30 partial sums
#define SMF  (REDS + 8*30)
#define SMEM_BYTES (SMF*4)

struct WPtrs { const float* p[20]; };

__device__ double g_acc[32];          // S0[2], S1[2][4], S2[2][10]
__device__ float4 g_z4[MAXB];         // per-row z
__device__ float  g_cp[24];           // mu[2][4], r[2][4], coef[2], maxval

typedef unsigned long long u64;

__device__ __forceinline__ void ffma2(u64& acc, u64 a, u64 b) {
    asm("fma.rn.f32x2 %0, %1, %2, %0;" : "+l"(acc) : "l"(a), "l"(b));
}
__device__ __forceinline__ u64 pack2(float v) {
    u64 r; unsigned int u = __float_as_uint(v);
    asm("mov.b64 %0, {%1, %1};" : "=l"(r) : "r"(u));
    return r;
}
__device__ __forceinline__ float2 unpack2(u64 p) {
    unsigned int lo, hi;
    asm("mov.b64 {%0, %1}, %2;" : "=r"(lo), "=r"(hi) : "l"(p));
    return make_float2(__uint_as_float(lo), __uint_as_float(hi));
}
__device__ __forceinline__ float ftanh(float x) {
    float c = fminf(fmaxf(x, -15.f), 15.f);
    float e = __expf(2.f * c);
    return 1.f - __fdividef(2.f, e + 1.f);
}

__device__ __forceinline__ void cpW(float* sm, int off, const float* g,
                                    int rows, int cols, int colsP) {
    for (int i = threadIdx.x; i < rows * cols; i += blockDim.x)
        sm[off + (i / cols) * colsP + (i % cols)] = g[i];
}

__global__ void zero_acc_kernel() {
    if (threadIdx.x < 32) g_acc[threadIdx.x] = 0.0;
}

__global__ void __launch_bounds__(T1, 1)
pass1_kernel(const float* __restrict__ x, float* __restrict__ out,
             int Bt, WPtrs W) {
    extern __shared__ float sm[];
    const int tid = threadIdx.x;
    const long long base = (long long)blockIdx.x * T1;
    long long rem = (long long)Bt - base;
    int rowsv = rem < 0 ? 0 : (rem > T1 ? T1 : (int)rem);

    // zero weight pads + x tile
    for (int i = tid; i < XS + T1 * XSTR; i += T1) sm[i] = 0.f;
    __syncthreads();

    cpW(sm, EW0, W.p[0], 118, 60, 60);
    cpW(sm, EB0, W.p[1], 1, 60, 60);
    cpW(sm, EW1, W.p[2], 60, 30, 32);
    cpW(sm, EB1, W.p[3], 1, 30, 32);
    cpW(sm, EW2, W.p[4], 30, 10, 12);
    cpW(sm, EB2, W.p[5], 1, 10, 12);
    cpW(sm, EW3, W.p[6], 10, 1, 1);
    cpW(sm, EB3, W.p[7], 1, 1, 1);
    cpW(sm, DW0, W.p[8], 1, 10, 10);
    cpW(sm, DB0, W.p[9], 1, 10, 10);
    cpW(sm, DW1, W.p[10], 10, 30, 32);
    cpW(sm, DB1, W.p[11], 1, 30, 32);
    cpW(sm, DW2, W.p[12], 30, 60, 60);
    cpW(sm, DB2, W.p[13], 1, 60, 60);
    cpW(sm, DW3, W.p[14], 60, 118, 120);
    cpW(sm, DB3, W.p[15], 1, 118, 120);
    cpW(sm, SW0, W.p[16], 4, 10, 10);
    cpW(sm, SB0, W.p[17], 1, 10, 10);
    cpW(sm, SW1, W.p[18], 10, 2, 2);
    cpW(sm, SB1, W.p[19], 1, 2, 2);
    for (int i = tid; i < rowsv * 118; i += T1) {
        int r = i / 118, c = i % 118;
        sm[XS + r * XSTR + c] = x[(base + r) * 118 + c];
    }
    __syncthreads();

    float* xr = sm + XS + tid * XSTR;

    // ---- encoder L1: 118 -> 60, relu (packed f32x2) ----
    u64 a1[30];
#pragma unroll
    for (int u = 0; u < 30; ++u) a1[u] = *(const u64*)(sm + EB0 + 2 * u);
    float sx = 0.f, sx2 = 0.f;
#pragma unroll 2
    for (int j = 0; j < 118; ++j) {
        float xv = xr[j];
        sx += xv; sx2 = fmaf(xv, xv, sx2);
        u64 xp = pack2(xv);
        const ulonglong2* w = (const ulonglong2*)(sm + EW0 + j * 60);
#pragma unroll
        for (int u = 0; u < 15; ++u) {
            ulonglong2 wv = w[u];
            ffma2(a1[2*u], xp, wv.x); ffma2(a1[2*u+1], xp, wv.y);
        }
    }
    float h1[60];
#pragma unroll
    for (int u = 0; u < 30; ++u) {
        float2 f = unpack2(a1[u]);
        h1[2*u] = fmaxf(f.x, 0.f); h1[2*u+1] = fmaxf(f.y, 0.f);
    }

    // ---- encoder L2: 60 -> 30(pad 32), relu ----
    u64 a2[16];
#pragma unroll
    for (int u = 0; u < 16; ++u) a2[u] = *(const u64*)(sm + EB1 + 2 * u);
#pragma unroll 2
    for (int j = 0; j < 60; ++j) {
        u64 vp = pack2(h1[j]);
        const ulonglong2* w = (const ulonglong2*)(sm + EW1 + j * 32);
#pragma unroll
        for (int u = 0; u < 8; ++u) {
            ulonglong2 wv = w[u];
            ffma2(a2[2*u], vp, wv.x); ffma2(a2[2*u+1], vp, wv.y);
        }
    }
    float h2[32];
#pragma unroll
    for (int u = 0; u < 16; ++u) {
        float2 f = unpack2(a2[u]);
        h2[2*u] = fmaxf(f.x, 0.f); h2[2*u+1] = fmaxf(f.y, 0.f);
    }

    // ---- encoder L3: 30 -> 10(pad 12), relu ----
    u64 a3[6];
#pragma unroll
    for (int u = 0; u < 6; ++u) a3[u] = *(const u64*)(sm + EB2 + 2 * u);
#pragma unroll
    for (int j = 0; j < 30; ++j) {
        u64 vp = pack2(h2[j]);
        const ulonglong2* w = (const ulonglong2*)(sm + EW2 + j * 12);
#pragma unroll
        for (int u = 0; u < 3; ++u) {
            ulonglong2 wv = w[u];
            ffma2(a3[2*u], vp, wv.x); ffma2(a3[2*u+1], vp, wv.y);
        }
    }
    float h3[12];
#pragma unroll
    for (int u = 0; u < 6; ++u) {
        float2 f = unpack2(a3[u]);
        h3[2*u] = fmaxf(f.x, 0.f); h3[2*u+1] = fmaxf(f.y, 0.f);
    }

    // ---- enc: 10 -> 1 ----
    float e = sm[EB3];
#pragma unroll
    for (int j = 0; j < 10; ++j) e = fmaf(h3[j], sm[EW3 + j], e);

    // ---- decoder L1: 1 -> 10, tanh ----
    float d1v[10];
#pragma unroll
    for (int k = 0; k < 10; ++k) d1v[k] = ftanh(fmaf(e, sm[DW0 + k], sm[DB0 + k]));

    // ---- decoder L2: 10 -> 30(pad 32), tanh ----
    u64 a4[16];
#pragma unroll
    for (int u = 0; u < 16; ++u) a4[u] = *(const u64*)(sm + DB1 + 2 * u);
#pragma unroll
    for (int j = 0; j < 10; ++j) {
        u64 vp = pack2(d1v[j]);
        const ulonglong2* w = (const ulonglong2*)(sm + DW1 + j * 32);
#pragma unroll
        for (int u = 0; u < 8; ++u) {
            ulonglong2 wv = w[u];
            ffma2(a4[2*u], vp, wv.x); ffma2(a4[2*u+1], vp, wv.y);
        }
    }
    float d2[30];
#pragma unroll
    for (int u = 0; u < 15; ++u) {
        float2 f = unpack2(a4[u]);
        d2[2*u] = ftanh(f.x); d2[2*u+1] = ftanh(f.y);
    }

    // ---- decoder L3: 30 -> 60, tanh ----
    u64 a5[30];
#pragma unroll
    for (int u = 0; u < 30; ++u) a5[u] = *(const u64*)(sm + DB2 + 2 * u);
#pragma unroll 2
    for (int j = 0; j < 30; ++j) {
        u64 vp = pack2(d2[j]);
        const ulonglong2* w = (const ulonglong2*)(sm + DW2 + j * 60);
#pragma unroll
        for (int u = 0; u < 15; ++u) {
            ulonglong2 wv = w[u];
            ffma2(a5[2*u], vp, wv.x); ffma2(a5[2*u+1], vp, wv.y);
        }
    }
    float d3[60];
#pragma unroll
    for (int u = 0; u < 30; ++u) {
        float2 f = unpack2(a5[u]);
        d3[2*u] = ftanh(f.x); d3[2*u+1] = ftanh(f.y);
    }

    // ---- decoder L4: 60 -> 118(pad 120), two 60-wide chunks ----
    float dot = 0.f, dn2 = 0.f, dd2 = 0.f;
#pragma unroll
    for (int c = 0; c < 2; ++c) {
        const int jo = c * 60;
        u64 a6[30];
#pragma unroll
        for (int u = 0; u < 30; ++u) a6[u] = *(const u64*)(sm + DB3 + jo + 2 * u);
#pragma unroll 2
        for (int k = 0; k < 60; ++k) {
            u64 vp = pack2(d3[k]);
            const ulonglong2* w = (const ulonglong2*)(sm + DW3 + k * 120 + jo);
#pragma unroll
            for (int u = 0; u < 15; ++u) {
                ulonglong2 wv = w[u];
                ffma2(a6[2*u], vp, wv.x); ffma2(a6[2*u+1], vp, wv.y);
            }
        }
#pragma unroll
        for (int u = 0; u < 30; ++u) {
            float2 f = unpack2(a6[u]);
            int i0 = jo + 2 * u;
            if (i0 < 118) {
                float xv = xr[i0];
                dot = fmaf(xv, f.x, dot); dn2 = fmaf(f.x, f.x, dn2);
                float df = xv - f.x; dd2 = fmaf(df, df, dd2);
                xr[i0] = f.x;
            }
            if (i0 + 1 < 118) {
                float xv = xr[i0 + 1];
                dot = fmaf(xv, f.y, dot); dn2 = fmaf(f.y, f.y, dn2);
                float df = xv - f.y; dd2 = fmaf(df, df, dd2);
                xr[i0 + 1] = f.y;
            }
        }
    }

    // ---- z features ----
    float xn = sqrtf(sx2);
    float dn = sqrtf(dn2);
    float rel = sqrtf(dd2) / fmaxf(xn, 1e-10f);
    float cs = dot / fmaxf(xn * dn, 1e-10f);
    float mean = sx * (1.f / 118.f);
    float var = sx2 * (1.f / 118.f) - mean * mean;
    float sd = sqrtf(fmaxf(var, 0.f));
    float z0 = e, z1 = rel, z2 = cs, z3 = sd;

    // ---- estimation net: 4 -> 10 tanh -> 2 softmax ----
    float l0 = sm[SB1], l1 = sm[SB1 + 1];
#pragma unroll
    for (int k = 0; k < 10; ++k) {
        float t = ftanh(z0 * sm[SW0 + k] + z1 * sm[SW0 + 10 + k] +
                        z2 * sm[SW0 + 20 + k] + z3 * sm[SW0 + 30 + k] +
                        sm[SB0 + k]);
        l0 = fmaf(t, sm[SW1 + 2 * k], l0);
        l1 = fmaf(t, sm[SW1 + 2 * k + 1], l1);
    }
    float mx = fmaxf(l0, l1);
    float e0 = __expf(l0 - mx), e1 = __expf(l1 - mx);
    float sinv = __fdividef(1.f, e0 + e1);
    float gg0 = e0 * sinv, gg1 = e1 * sinv;

    bool valid = tid < rowsv;
    if (valid) {
        g_z4[base + tid] = make_float4(z0, z1, z2, z3);
    } else {
        gg0 = gg1 = 0.f; z0 = z1 = z2 = z3 = 0.f;
    }

    // ---- 30-way reduction: warp shuffle -> smem stage -> 30 atomics/block ----
    float red[30];
    red[0] = gg0; red[1] = gg1;
    red[2] = gg0 * z0; red[3] = gg0 * z1; red[4] = gg0 * z2; red[5] = gg0 * z3;
    red[6] = gg1 * z0; red[7] = gg1 * z1; red[8] = gg1 * z2; red[9] = gg1 * z3;
    {
        float zz[10] = { z0*z0, z0*z1, z0*z2, z0*z3, z1*z1,
                         z1*z2, z1*z3, z2*z2, z2*z3, z3*z3 };
#pragma unroll
        for (int p = 0; p < 10; ++p) { red[10+p] = gg0*zz[p]; red[20+p] = gg1*zz[p]; }
    }
    const int wid = tid >> 5;
#pragma unroll
    for (int r = 0; r < 30; ++r) {
        float v = red[r];
        v += __shfl_xor_sync(0xffffffffu, v, 16);
        v += __shfl_xor_sync(0xffffffffu, v, 8);
        v += __shfl_xor_sync(0xffffffffu, v, 4);
        v += __shfl_xor_sync(0xffffffffu, v, 2);
        v += __shfl_xor_sync(0xffffffffu, v, 1);
        if ((tid & 31) == 0) sm[REDS + wid * 30 + r] = v;
    }

    __syncthreads();
    if (tid < 30) {
        float s = 0.f;
#pragma unroll
        for (int w = 0; w < 8; ++w) s += sm[REDS + w * 30 + tid];
        atomicAdd(&g_acc[tid], (double)s);
    }
    // coalesced dec store (x tile now holds dec)
    for (int i = tid; i < rowsv * 118; i += T1) {
        int r = i / 118, c = i % 118;
        out[(base + r) * 118 + c] = sm[XS + r * XSTR + c];
    }
}

__device__ double inv4x4(const double m[16], double inv[16]) {
    inv[0]  =  m[5]*m[10]*m[15] - m[5]*m[11]*m[14] - m[9]*m[6]*m[15] + m[9]*m[7]*m[14] + m[13]*m[6]*m[11] - m[13]*m[7]*m[10];
    inv[4]  = -m[4]*m[10]*m[15] + m[4]*m[11]*m[14] + m[8]*m[6]*m[15] - m[8]*m[7]*m[14] - m[12]*m[6]*m[11] + m[12]*m[7]*m[10];
    inv[8]  =  m[4]*m[9]*m[15]  - m[4]*m[11]*m[13] - m[8]*m[5]*m[15] + m[8]*m[7]*m[13] + m[12]*m[5]*m[11] - m[12]*m[7]*m[9];
    inv[12] = -m[4]*m[9]*m[14]  + m[4]*m[10]*m[13] + m[8]*m[5]*m[14] - m[8]*m[6]*m[13] - m[12]*m[5]*m[10] + m[12]*m[6]*m[9];
    inv[1]  = -m[1]*m[10]*m[15] + m[1]*m[11]*m[14] + m[9]*m[2]*m[15] - m[9]*m[3]*m[14] - m[13]*m[2]*m[11] + m[13]*m[3]*m[10];
    inv[5]  =  m[0]*m[10]*m[15] - m[0]*m[11]*m[14] - m[8]*m[2]*m[15] + m[8]*m[3]*m[14] + m[12]*m[2]*m[11] - m[12]*m[3]*m[10];
    inv[9]  = -m[0]*m[9]*m[15]  + m[0]*m[11]*m[13] + m[8]*m[1]*m[15] - m[8]*m[3]*m[13] - m[12]*m[1]*m[11] + m[12]*m[3]*m[9];
    inv[13] =  m[0]*m[9]*m[14]  - m[0]*m[10]*m[13] - m[8]*m[1]*m[14] + m[8]*m[2]*m[13] + m[12]*m[1]*m[10] - m[12]*m[2]*m[9];
    inv[2]  =  m[1]*m[6]*m[15]  - m[1]*m[7]*m[14]  - m[5]*m[2]*m[15] + m[5]*m[3]*m[14] + m[13]*m[2]*m[7]  - m[13]*m[3]*m[6];
    inv[6]  = -m[0]*m[6]*m[15]  + m[0]*m[7]*m[14]  + m[4]*m[2]*m[15] - m[4]*m[3]*m[14] - m[12]*m[2]*m[7]  + m[12]*m[3]*m[6];
    inv[10] =  m[0]*m[5]*m[15]  - m[0]*m[7]*m[13]  - m[4]*m[1]*m[15] + m[4]*m[3]*m[13] + m[12]*m[1]*m[7]  - m[12]*m[3]*m[5];
    inv[14] = -m[0]*m[5]*m[14]  + m[0]*m[6]*m[13]  + m[4]*m[1]*m[14] - m[4]*m[2]*m[13] - m[12]*m[1]*m[6]  + m[12]*m[2]*m[5];
    inv[3]  = -m[1]*m[6]*m[11]  + m[1]*m[7]*m[10]  + m[5]*m[2]*m[11] - m[5]*m[3]*m[10] - m[9]*m[2]*m[7]   + m[9]*m[3]*m[6];
    inv[7]  =  m[0]*m[6]*m[11]  - m[0]*m[7]*m[10]  - m[4]*m[2]*m[11] + m[4]*m[3]*m[10] + m[8]*m[2]*m[7]   - m[8]*m[3]*m[6];
    inv[11] = -m[0]*m[5]*m[11]  + m[0]*m[7]*m[9]   + m[4]*m[1]*m[11] - m[4]*m[3]*m[9]  - m[8]*m[1]*m[7]   + m[8]*m[3]*m[5];
    inv[15] =  m[0]*m[5]*m[10]  - m[0]*m[6]*m[9]   - m[4]*m[1]*m[10] + m[4]*m[2]*m[9]  + m[8]*m[1]*m[6]   - m[8]*m[2]*m[5];
    double det = m[0]*inv[0] + m[1]*inv[4] + m[2]*inv[8] + m[3]*inv[12];
    double id = 1.0 / det;
    for (int i = 0; i < 16; ++i) inv[i] *= id;
    return det;
}

__global__ void pass2_kernel(float* out, int Bt) {
    if (blockIdx.x != 0 || threadIdx.x != 0) return;
    double Sg[2], S1[2][4], S2[2][10];
    Sg[0] = g_acc[0]; Sg[1] = g_acc[1];
    for (int k = 0; k < 2; ++k) {
        for (int c = 0; c < 4; ++c) S1[k][c] = g_acc[2 + k * 4 + c];
        for (int p = 0; p < 10; ++p) S2[k][p] = g_acc[10 + k * 10 + p];
    }
    const int pi[10] = {0,0,0,0,1,1,1,2,2,3};
    const int pj[10] = {0,1,2,3,1,2,3,2,3,3};
    double mu[2][4], rr[2][4], coef[2];
    double covdiag = 0.0;
    const double TP = 6.283185307179586476925287;
    const double scale4 = TP * TP * TP * TP;
    for (int k = 0; k < 2; ++k) {
        for (int c = 0; c < 4; ++c) mu[k][c] = S1[k][c] / Sg[k];
        double m[16];
        for (int p = 0; p < 10; ++p) {
            double cv = S2[k][p] / Sg[k] - mu[k][pi[p]] * mu[k][pj[p]];
            if (pi[p] == pj[p]) cv += 1e-12;
            m[pi[p] * 4 + pj[p]] = cv;
            m[pj[p] * 4 + pi[p]] = cv;
        }
        for (int i = 0; i < 4; ++i) covdiag += 1.0 / m[i * 4 + i];
        double inv[16];
        double det = inv4x4(m, inv);
        double detcov = det * scale4;
        double phi = Sg[k] / (double)Bt;
        coef[k] = phi / (sqrt(detcov) + 1e-12);
        for (int g = 0; g < 4; ++g)
            rr[k][g] = inv[g*4+0] + inv[g*4+1] + inv[g*4+2] + inv[g*4+3];
    }
    float4 zf = g_z4[0];
    double z0[4] = { zf.x, zf.y, zf.z, zf.w };
    double mv = 0.0;
    for (int k = 0; k < 2; ++k) {
        double s1 = 0.0, dot = 0.0;
        for (int c = 0; c < 4; ++c) {
            double zm = z0[c] - mu[k][c];
            s1 += zm; dot += zm * rr[k][c];
        }
        double ett = -0.5 * dot * s1;
        if (ett > mv) mv = ett;
    }
    for (int k = 0; k < 2; ++k) {
        for (int c = 0; c < 4; ++c) {
            g_cp[k * 4 + c] = (float)mu[k][c];
            g_cp[8 + k * 4 + c] = (float)rr[k][c];
        }
        g_cp[16 + k] = (float)coef[k];
    }
    g_cp[18] = (float)mv;
    out[(size_t)Bt * 118 + Bt] = (float)covdiag;
}

__global__ void pass3_kernel(float* __restrict__ out, int Bt) {
    int b = blockIdx.x * blockDim.x + threadIdx.x;
    if (b >= Bt) return;
    float4 z = g_z4[b];
    float mv = g_cp[18];
    float s = 0.f;
#pragma unroll
    for (int k = 0; k < 2; ++k) {
        float zm0 = z.x - g_cp[k*4+0];
        float zm1 = z.y - g_cp[k*4+1];
        float zm2 = z.z - g_cp[k*4+2];
        float zm3 = z.w - g_cp[k*4+3];
        float s1 = zm0 + zm1 + zm2 + zm3;
        float dot = zm0 * g_cp[8+k*4+0] + zm1 * g_cp[8+k*4+1] +
                    zm2 * g_cp[8+k*4+2] + zm3 * g_cp[8+k*4+3];
        float ett = -0.5f * dot * s1;
        float t = fminf(fmaxf(ett - mv, -50.f), 50.f);
        s += g_cp[16+k] * expf(t);
    }
    out[(size_t)Bt * 118 + b] = -mv - logf(s + 1e-12f);
}

extern "C" void kernel_launch(void* const* d_in, const int* in_sizes, int n_in,
                              void* d_out, int out_size) {
    const float* x = (const float*)d_in[0];
    WPtrs W;
    for (int i = 0; i < 20; ++i) W.p[i] = (const float*)d_in[1 + i];
    int Bt = in_sizes[0] / 118;
    if (Bt > MAXB) Bt = MAXB;
    float* out = (float*)d_out;

    (void)cudaFuncSetAttribute(pass1_kernel,
                               cudaFuncAttributeMaxDynamicSharedMemorySize,
                               SMEM_BYTES);

    zero_acc_kernel<<<1, 32>>>();
    int grid = (Bt + T1 - 1) / T1;
    pass1_kernel<<<grid, T1, SMEM_BYTES>>>(x, out, Bt, W);
    pass2_kernel<<<1, 1>>>(out, Bt);
    pass3_kernel<<<(Bt + 255) / 256, 256>>>(out, Bt);
}

// round 12
// speedup vs baseline: 1.3381x; 1.0316x over previous
#include <cuda_runtime.h>
#include <math.h>

#define D_INPUT 118
#define MAXB 524288
#define T1 384

// -------- smem layout (float offsets) --------
#define EW0 0        // 118x60
#define EB0 7080     // 60
#define EW1 7140     // 60x32 (pad of 30)
#define EB1 9060     // 32
#define EW2 9092     // 30x12 (pad of 10)
#define EB2 9452     // 12
#define EW3 9464     // 12 (10 used)
#define EB3 9476     // 4 (1 used)
#define DW0 9480     // 12 (10 used)
#define DB0 9492     // 12
#define DW1 9504     // 10x32 (pad of 30)
#define DB1 9824     // 32
#define DW2 9856     // 30x60
#define DB2 11656    // 60
#define DW3 11716    // 60x120 (pad of 118)
#define DB3 18916    // 120
#define SW0 19036    // 4x10
#define SB0 19076    // 12 (10)
#define SW1 19088    // 10x2
#define SB1 19108    // 4 (2)
#define WTOT 19112
#define XCH 19112            // chunk buffer: T1 rows x 32 cols, stride 33
#define XSTR2 33
#define REDS (XCH + T1*XSTR2)   // 12 warps x 30 partial sums
#define SMF  (REDS + 12*30)
#define SMEM_BYTES (SMF*4)

struct WPtrs { const float* p[20]; };

__device__ double g_acc[32];          // S0[2], S1[2][4], S2[2][10]
__device__ float4 g_z4[MAXB];         // per-row z
__device__ float  g_cp[24];           // mu[2][4], r[2][4], coef[2], maxval

typedef unsigned long long u64;

__device__ __forceinline__ void ffma2(u64& acc, u64 a, u64 b) {
    asm("fma.rn.f32x2 %0, %1, %2, %0;" : "+l"(acc) : "l"(a), "l"(b));
}
__device__ __forceinline__ u64 pack2(float v) {
    u64 r; unsigned int u = __float_as_uint(v);
    asm("mov.b64 %0, {%1, %1};" : "=l"(r) : "r"(u));
    return r;
}
__device__ __forceinline__ float2 unpack2(u64 p) {
    unsigned int lo, hi;
    asm("mov.b64 {%0, %1}, %2;" : "=r"(lo), "=r"(hi) : "l"(p));
    return make_float2(__uint_as_float(lo), __uint_as_float(hi));
}
__device__ __forceinline__ float ftanh(float x) {
    float c = fminf(fmaxf(x, -15.f), 15.f);
    float e = __expf(2.f * c);
    return 1.f - __fdividef(2.f, e + 1.f);
}

__device__ __forceinline__ void cpW(float* sm, int off, const float* g,
                                    int rows, int cols, int colsP) {
    for (int i = threadIdx.x; i < rows * cols; i += blockDim.x)
        sm[off + (i / cols) * colsP + (i % cols)] = g[i];
}

__global__ void zero_acc_kernel() {
    if (threadIdx.x < 32) g_acc[threadIdx.x] = 0.0;
}

__global__ void __launch_bounds__(T1, 1)
pass1_kernel(const float* __restrict__ x, float* __restrict__ out,
             int Bt, WPtrs W) {
    extern __shared__ float sm[];
    const int tid = threadIdx.x;
    const long long base = (long long)blockIdx.x * T1;
    long long rem = (long long)Bt - base;
    int rowsv = rem < 0 ? 0 : (rem > T1 ? T1 : (int)rem);

    // zero weight region (pads must be 0)
    for (int i = tid; i < WTOT; i += T1) sm[i] = 0.f;
    __syncthreads();

    cpW(sm, EW0, W.p[0], 118, 60, 60);
    cpW(sm, EB0, W.p[1], 1, 60, 60);
    cpW(sm, EW1, W.p[2], 60, 30, 32);
    cpW(sm, EB1, W.p[3], 1, 30, 32);
    cpW(sm, EW2, W.p[4], 30, 10, 12);
    cpW(sm, EB2, W.p[5], 1, 10, 12);
    cpW(sm, EW3, W.p[6], 10, 1, 1);
    cpW(sm, EB3, W.p[7], 1, 1, 1);
    cpW(sm, DW0, W.p[8], 1, 10, 10);
    cpW(sm, DB0, W.p[9], 1, 10, 10);
    cpW(sm, DW1, W.p[10], 10, 30, 32);
    cpW(sm, DB1, W.p[11], 1, 30, 32);
    cpW(sm, DW2, W.p[12], 30, 60, 60);
    cpW(sm, DB2, W.p[13], 1, 60, 60);
    cpW(sm, DW3, W.p[14], 60, 118, 120);
    cpW(sm, DB3, W.p[15], 1, 118, 120);
    cpW(sm, SW0, W.p[16], 4, 10, 10);
    cpW(sm, SB0, W.p[17], 1, 10, 10);
    cpW(sm, SW1, W.p[18], 10, 2, 2);
    cpW(sm, SB1, W.p[19], 1, 2, 2);

    float* xc = sm + XCH + tid * XSTR2;

    // ---- encoder L1: 118 -> 60, relu; x streamed in 4 chunks of 32 cols ----
    u64 a1[30];
#pragma unroll
    for (int u = 0; u < 30; ++u) a1[u] = *(const u64*)(sm + EB0 + 2 * u);
    float sx = 0.f, sx2 = 0.f;
    for (int ch = 0; ch < 4; ++ch) {
        const int c0 = ch * 32;
        __syncthreads();   // previous chunk fully consumed
        for (int i = tid; i < T1 * 32; i += T1) {
            int r = i >> 5, c = i & 31;
            int gc = c0 + c;
            float v = (r < rowsv && gc < 118) ? x[(base + r) * 118 + gc] : 0.f;
            sm[XCH + r * XSTR2 + c] = v;
        }
        __syncthreads();
#pragma unroll
        for (int j = 0; j < 32; ++j) {
            float xv = xc[j];
            sx += xv; sx2 = fmaf(xv, xv, sx2);
            u64 xp = pack2(xv);
            const ulonglong2* w = (const ulonglong2*)(sm + EW0 + (c0 + j) * 60);
#pragma unroll
            for (int u = 0; u < 15; ++u) {
                ulonglong2 wv = w[u];
                ffma2(a1[2*u], xp, wv.x); ffma2(a1[2*u+1], xp, wv.y);
            }
        }
    }
    float h1[60];
#pragma unroll
    for (int u = 0; u < 30; ++u) {
        float2 f = unpack2(a1[u]);
        h1[2*u] = fmaxf(f.x, 0.f); h1[2*u+1] = fmaxf(f.y, 0.f);
    }

    // ---- encoder L2: 60 -> 30(pad 32), relu ----
    u64 a2[16];
#pragma unroll
    for (int u = 0; u < 16; ++u) a2[u] = *(const u64*)(sm + EB1 + 2 * u);
#pragma unroll 2
    for (int j = 0; j < 60; ++j) {
        u64 vp = pack2(h1[j]);
        const ulonglong2* w = (const ulonglong2*)(sm + EW1 + j * 32);
#pragma unroll
        for (int u = 0; u < 8; ++u) {
            ulonglong2 wv = w[u];
            ffma2(a2[2*u], vp, wv.x); ffma2(a2[2*u+1], vp, wv.y);
        }
    }
    float h2[32];
#pragma unroll
    for (int u = 0; u < 16; ++u) {
        float2 f = unpack2(a2[u]);
        h2[2*u] = fmaxf(f.x, 0.f); h2[2*u+1] = fmaxf(f.y, 0.f);
    }

    // ---- encoder L3: 30 -> 10(pad 12), relu ----
    u64 a3[6];
#pragma unroll
    for (int u = 0; u < 6; ++u) a3[u] = *(const u64*)(sm + EB2 + 2 * u);
#pragma unroll
    for (int j = 0; j < 30; ++j) {
        u64 vp = pack2(h2[j]);
        const ulonglong2* w = (const ulonglong2*)(sm + EW2 + j * 12);
#pragma unroll
        for (int u = 0; u < 3; ++u) {
            ulonglong2 wv = w[u];
            ffma2(a3[2*u], vp, wv.x); ffma2(a3[2*u+1], vp, wv.y);
        }
    }
    float h3[12];
#pragma unroll
    for (int u = 0; u < 6; ++u) {
        float2 f = unpack2(a3[u]);
        h3[2*u] = fmaxf(f.x, 0.f); h3[2*u+1] = fmaxf(f.y, 0.f);
    }

    // ---- enc: 10 -> 1 ----
    float e = sm[EB3];
#pragma unroll
    for (int j = 0; j < 10; ++j) e = fmaf(h3[j], sm[EW3 + j], e);

    // ---- decoder L1: 1 -> 10, tanh ----
    float d1v[10];
#pragma unroll
    for (int k = 0; k < 10; ++k) d1v[k] = ftanh(fmaf(e, sm[DW0 + k], sm[DB0 + k]));

    // ---- decoder L2: 10 -> 30(pad 32), tanh ----
    u64 a4[16];
#pragma unroll
    for (int u = 0; u < 16; ++u) a4[u] = *(const u64*)(sm + DB1 + 2 * u);
#pragma unroll
    for (int j = 0; j < 10; ++j) {
        u64 vp = pack2(d1v[j]);
        const ulonglong2* w = (const ulonglong2*)(sm + DW1 + j * 32);
#pragma unroll
        for (int u = 0; u < 8; ++u) {
            ulonglong2 wv = w[u];
            ffma2(a4[2*u], vp, wv.x); ffma2(a4[2*u+1], vp, wv.y);
        }
    }
    float d2[30];
#pragma unroll
    for (int u = 0; u < 15; ++u) {
        float2 f = unpack2(a4[u]);
        d2[2*u] = ftanh(f.x); d2[2*u+1] = ftanh(f.y);
    }

    // ---- decoder L3: 30 -> 60, tanh ----
    u64 a5[30];
#pragma unroll
    for (int u = 0; u < 30; ++u) a5[u] = *(const u64*)(sm + DB2 + 2 * u);
#pragma unroll 2
    for (int j = 0; j < 30; ++j) {
        u64 vp = pack2(d2[j]);
        const ulonglong2* w = (const ulonglong2*)(sm + DW2 + j * 60);
#pragma unroll
        for (int u = 0; u < 15; ++u) {
            ulonglong2 wv = w[u];
            ffma2(a5[2*u], vp, wv.x); ffma2(a5[2*u+1], vp, wv.y);
        }
    }
    float d3[60];
#pragma unroll
    for (int u = 0; u < 30; ++u) {
        float2 f = unpack2(a5[u]);
        d3[2*u] = ftanh(f.x); d3[2*u+1] = ftanh(f.y);
    }

    // ---- decoder L4: 60 -> 118, chunked over 4x32 output cols; x re-streamed ----
    float dot = 0.f, dn2 = 0.f, dd2 = 0.f;
    for (int ch = 0; ch < 4; ++ch) {
        const int c0 = ch * 32;
        __syncthreads();   // previous chunk stored / buffer free
        for (int i = tid; i < T1 * 32; i += T1) {
            int r = i >> 5, c = i & 31;
            int gc = c0 + c;
            float v = (r < rowsv && gc < 118) ? x[(base + r) * 118 + gc] : 0.f;
            sm[XCH + r * XSTR2 + c] = v;
        }
        __syncthreads();
        u64 a6[16];
#pragma unroll
        for (int u = 0; u < 16; ++u) a6[u] = *(const u64*)(sm + DB3 + c0 + 2 * u);
#pragma unroll 2
        for (int k = 0; k < 60; ++k) {
            u64 vp = pack2(d3[k]);
            const ulonglong2* w = (const ulonglong2*)(sm + DW3 + k * 120 + c0);
#pragma unroll
            for (int u = 0; u < 8; ++u) {
                ulonglong2 wv = w[u];
                ffma2(a6[2*u], vp, wv.x); ffma2(a6[2*u+1], vp, wv.y);
            }
        }
#pragma unroll
        for (int u = 0; u < 16; ++u) {
            float2 f = unpack2(a6[u]);
            int i0 = c0 + 2 * u;
            if (i0 < 118) {
                float xv = xc[2*u];
                dot = fmaf(xv, f.x, dot); dn2 = fmaf(f.x, f.x, dn2);
                float df = xv - f.x; dd2 = fmaf(df, df, dd2);
                xc[2*u] = f.x;       // overwrite chunk with dec for coalesced store
            }
            if (i0 + 1 < 118) {
                float xv = xc[2*u+1];
                dot = fmaf(xv, f.y, dot); dn2 = fmaf(f.y, f.y, dn2);
                float df = xv - f.y; dd2 = fmaf(df, df, dd2);
                xc[2*u+1] = f.y;
            }
        }
        __syncthreads();
        int cw = 118 - c0; if (cw > 32) cw = 32;
        for (int i = tid; i < rowsv * cw; i += T1) {
            int r = i / cw, c = i % cw;
            out[(base + r) * 118 + c0 + c] = sm[XCH + r * XSTR2 + c];
        }
    }

    // ---- z features ----
    float xn = sqrtf(sx2);
    float dn = sqrtf(dn2);
    float rel = sqrtf(dd2) / fmaxf(xn, 1e-10f);
    float cs = dot / fmaxf(xn * dn, 1e-10f);
    float mean = sx * (1.f / 118.f);
    float var = sx2 * (1.f / 118.f) - mean * mean;
    float sd = sqrtf(fmaxf(var, 0.f));
    float z0 = e, z1 = rel, z2 = cs, z3 = sd;

    // ---- estimation net: 4 -> 10 tanh -> 2 softmax ----
    float l0 = sm[SB1], l1 = sm[SB1 + 1];
#pragma unroll
    for (int k = 0; k < 10; ++k) {
        float t = ftanh(z0 * sm[SW0 + k] + z1 * sm[SW0 + 10 + k] +
                        z2 * sm[SW0 + 20 + k] + z3 * sm[SW0 + 30 + k] +
                        sm[SB0 + k]);
        l0 = fmaf(t, sm[SW1 + 2 * k], l0);
        l1 = fmaf(t, sm[SW1 + 2 * k + 1], l1);
    }
    float mx = fmaxf(l0, l1);
    float e0 = __expf(l0 - mx), e1 = __expf(l1 - mx);
    float sinv = __fdividef(1.f, e0 + e1);
    float gg0 = e0 * sinv, gg1 = e1 * sinv;

    bool valid = tid < rowsv;
    if (valid) {
        g_z4[base + tid] = make_float4(z0, z1, z2, z3);
    } else {
        gg0 = gg1 = 0.f; z0 = z1 = z2 = z3 = 0.f;
    }

    // ---- 30-way reduction: warp shuffle -> smem stage -> 30 atomics/block ----
    float red[30];
    red[0] = gg0; red[1] = gg1;
    red[2] = gg0 * z0; red[3] = gg0 * z1; red[4] = gg0 * z2; red[5] = gg0 * z3;
    red[6] = gg1 * z0; red[7] = gg1 * z1; red[8] = gg1 * z2; red[9] = gg1 * z3;
    {
        float zz[10] = { z0*z0, z0*z1, z0*z2, z0*z3, z1*z1,
                         z1*z2, z1*z3, z2*z2, z2*z3, z3*z3 };
#pragma unroll
        for (int p = 0; p < 10; ++p) { red[10+p] = gg0*zz[p]; red[20+p] = gg1*zz[p]; }
    }
    const int wid = tid >> 5;
#pragma unroll
    for (int r = 0; r < 30; ++r) {
        float v = red[r];
        v += __shfl_xor_sync(0xffffffffu, v, 16);
        v += __shfl_xor_sync(0xffffffffu, v, 8);
        v += __shfl_xor_sync(0xffffffffu, v, 4);
        v += __shfl_xor_sync(0xffffffffu, v, 2);
        v += __shfl_xor_sync(0xffffffffu, v, 1);
        if ((tid & 31) == 0) sm[REDS + wid * 30 + r] = v;
    }

    __syncthreads();
    if (tid < 30) {
        float s = 0.f;
#pragma unroll
        for (int w = 0; w < 12; ++w) s += sm[REDS + w * 30 + tid];
        atomicAdd(&g_acc[tid], (double)s);
    }
}

__device__ double inv4x4(const double m[16], double inv[16]) {
    inv[0]  =  m[5]*m[10]*m[15] - m[5]*m[11]*m[14] - m[9]*m[6]*m[15] + m[9]*m[7]*m[14] + m[13]*m[6]*m[11] - m[13]*m[7]*m[10];
    inv[4]  = -m[4]*m[10]*m[15] + m[4]*m[11]*m[14] + m[8]*m[6]*m[15] - m[8]*m[7]*m[14] - m[12]*m[6]*m[11] + m[12]*m[7]*m[10];
    inv[8]  =  m[4]*m[9]*m[15]  - m[4]*m[11]*m[13] - m[8]*m[5]*m[15] + m[8]*m[7]*m[13] + m[12]*m[5]*m[11] - m[12]*m[7]*m[9];
    inv[12] = -m[4]*m[9]*m[14]  + m[4]*m[10]*m[13] + m[8]*m[5]*m[14] - m[8]*m[6]*m[13] - m[12]*m[5]*m[10] + m[12]*m[6]*m[9];
    inv[1]  = -m[1]*m[10]*m[15] + m[1]*m[11]*m[14] + m[9]*m[2]*m[15] - m[9]*m[3]*m[14] - m[13]*m[2]*m[11] + m[13]*m[3]*m[10];
    inv[5]  =  m[0]*m[10]*m[15] - m[0]*m[11]*m[14] - m[8]*m[2]*m[15] + m[8]*m[3]*m[14] + m[12]*m[2]*m[11] - m[12]*m[3]*m[10];
    inv[9]  = -m[0]*m[9]*m[15]  + m[0]*m[11]*m[13] + m[8]*m[1]*m[15] - m[8]*m[3]*m[13] - m[12]*m[1]*m[11] + m[12]*m[3]*m[9];
    inv[13] =  m[0]*m[9]*m[14]  - m[0]*m[10]*m[13] - m[8]*m[1]*m[14] + m[8]*m[2]*m[13] + m[12]*m[1]*m[10] - m[12]*m[2]*m[9];
    inv[2]  =  m[1]*m[6]*m[15]  - m[1]*m[7]*m[14]  - m[5]*m[2]*m[15] + m[5]*m[3]*m[14] + m[13]*m[2]*m[7]  - m[13]*m[3]*m[6];
    inv[6]  = -m[0]*m[6]*m[15]  + m[0]*m[7]*m[14]  + m[4]*m[2]*m[15] - m[4]*m[3]*m[14] - m[12]*m[2]*m[7]  + m[12]*m[3]*m[6];
    inv[10] =  m[0]*m[5]*m[15]  - m[0]*m[7]*m[13]  - m[4]*m[1]*m[15] + m[4]*m[3]*m[13] + m[12]*m[1]*m[7]  - m[12]*m[3]*m[5];
    inv[14] = -m[0]*m[5]*m[14]  + m[0]*m[6]*m[13]  + m[4]*m[1]*m[14] - m[4]*m[2]*m[13] - m[12]*m[1]*m[6]  + m[12]*m[2]*m[5];
    inv[3]  = -m[1]*m[6]*m[11]  + m[1]*m[7]*m[10]  + m[5]*m[2]*m[11] - m[5]*m[3]*m[10] - m[9]*m[2]*m[7]   + m[9]*m[3]*m[6];
    inv[7]  =  m[0]*m[6]*m[11]  - m[0]*m[7]*m[10]  - m[4]*m[2]*m[11] + m[4]*m[3]*m[10] + m[8]*m[2]*m[7]   - m[8]*m[3]*m[6];
    inv[11] = -m[0]*m[5]*m[11]  + m[0]*m[7]*m[9]   + m[4]*m[1]*m[11] - m[4]*m[3]*m[9]  - m[8]*m[1]*m[7]   + m[8]*m[3]*m[5];
    inv[15] =  m[0]*m[5]*m[10]  - m[0]*m[6]*m[9]   - m[4]*m[1]*m[10] + m[4]*m[2]*m[9]  + m[8]*m[1]*m[6]   - m[8]*m[2]*m[5];
    double det = m[0]*inv[0] + m[1]*inv[4] + m[2]*inv[8] + m[3]*inv[12];
    double id = 1.0 / det;
    for (int i = 0; i < 16; ++i) inv[i] *= id;
    return det;
}

__global__ void pass2_kernel(float* out, int Bt) {
    if (blockIdx.x != 0 || threadIdx.x != 0) return;
    double Sg[2], S1[2][4], S2[2][10];
    Sg[0] = g_acc[0]; Sg[1] = g_acc[1];
    for (int k = 0; k < 2; ++k) {
        for (int c = 0; c < 4; ++c) S1[k][c] = g_acc[2 + k * 4 + c];
        for (int p = 0; p < 10; ++p) S2[k][p] = g_acc[10 + k * 10 + p];
    }
    const int pi[10] = {0,0,0,0,1,1,1,2,2,3};
    const int pj[10] = {0,1,2,3,1,2,3,2,3,3};
    double mu[2][4], rr[2][4], coef[2];
    double covdiag = 0.0;
    const double TP = 6.283185307179586476925287;
    const double scale4 = TP * TP * TP * TP;
    for (int k = 0; k < 2; ++k) {
        for (int c = 0; c < 4; ++c) mu[k][c] = S1[k][c] / Sg[k];
        double m[16];
        for (int p = 0; p < 10; ++p) {
            double cv = S2[k][p] / Sg[k] - mu[k][pi[p]] * mu[k][pj[p]];
            if (pi[p] == pj[p]) cv += 1e-12;
            m[pi[p] * 4 + pj[p]] = cv;
            m[pj[p] * 4 + pi[p]] = cv;
        }
        for (int i = 0; i < 4; ++i) covdiag += 1.0 / m[i * 4 + i];
        double inv[16];
        double det = inv4x4(m, inv);
        double detcov = det * scale4;
        double phi = Sg[k] / (double)Bt;
        coef[k] = phi / (sqrt(detcov) + 1e-12);
        for (int g = 0; g < 4; ++g)
            rr[k][g] = inv[g*4+0] + inv[g*4+1] + inv[g*4+2] + inv[g*4+3];
    }
    float4 zf = g_z4[0];
    double z0[4] = { zf.x, zf.y, zf.z, zf.w };
    double mv = 0.0;
    for (int k = 0; k < 2; ++k) {
        double s1 = 0.0, dot = 0.0;
        for (int c = 0; c < 4; ++c) {
            double zm = z0[c] - mu[k][c];
            s1 += zm; dot += zm * rr[k][c];
        }
        double ett = -0.5 * dot * s1;
        if (ett > mv) mv = ett;
    }
    for (int k = 0; k < 2; ++k) {
        for (int c = 0; c < 4; ++c) {
            g_cp[k * 4 + c] = (float)mu[k][c];
            g_cp[8 + k * 4 + c] = (float)rr[k][c];
        }
        g_cp[16 + k] = (float)coef[k];
    }
    g_cp[18] = (float)mv;
    out[(size_t)Bt * 118 + Bt] = (float)covdiag;
}

__global__ void pass3_kernel(float* __restrict__ out, int Bt) {
    int b = blockIdx.x * blockDim.x + threadIdx.x;
    if (b >= Bt) return;
    float4 z = g_z4[b];
    float mv = g_cp[18];
    float s = 0.f;
#pragma unroll
    for (int k = 0; k < 2; ++k) {
        float zm0 = z.x - g_cp[k*4+0];
        float zm1 = z.y - g_cp[k*4+1];
        float zm2 = z.z - g_cp[k*4+2];
        float zm3 = z.w - g_cp[k*4+3];
        float s1 = zm0 + zm1 + zm2 + zm3;
        float dot = zm0 * g_cp[8+k*4+0] + zm1 * g_cp[8+k*4+1] +
                    zm2 * g_cp[8+k*4+2] + zm3 * g_cp[8+k*4+3];
        float ett = -0.5f * dot * s1;
        float t = fminf(fmaxf(ett - mv, -50.f), 50.f);
        s += g_cp[16+k] * expf(t);
    }
    out[(size_t)Bt * 118 + b] = -mv - logf(s + 1e-12f);
}

extern "C" void kernel_launch(void* const* d_in, const int* in_sizes, int n_in,
                              void* d_out, int out_size) {
    const float* x = (const float*)d_in[0];
    WPtrs W;
    for (int i = 0; i < 20; ++i) W.p[i] = (const float*)d_in[1 + i];
    int Bt = in_sizes[0] / 118;
    if (Bt > MAXB) Bt = MAXB;
    float* out = (float*)d_out;

    (void)cudaFuncSetAttribute(pass1_kernel,
                               cudaFuncAttributeMaxDynamicSharedMemorySize,
                               SMEM_BYTES);

    zero_acc_kernel<<<1, 32>>>();
    int grid = (Bt + T1 - 1) / T1;
    pass1_kernel<<<grid, T1, SMEM_BYTES>>>(x, out, Bt, W);
    pass2_kernel<<<1, 1>>>(out, Bt);
    pass3_kernel<<<(Bt + 255) / 256, 256>>>(out, Bt);
}